// round 17
// baseline (speedup 1.0000x reference)
#include <cuda_runtime.h>
#include <cuda_fp16.h>
#include <math.h>

#define NMAX 100000
#define EMAX 1600000
#define NBLK ((NMAX + 255) / 256)   // 391

// Scratch (device globals; zero-initialized at module load — g_degi/g_status rely
// on this for the first run; later runs re-establish the invariants themselves)
__device__ __align__(16) int                g_degi[NMAX];
__device__ __align__(16) int                g_start[NMAX + 1];
__device__ __align__(16) unsigned long long g_status[NBLK];  // flag<<32 | blocksum
__device__ __align__(16) int                g_srcs[EMAX];
__device__ __align__(16) unsigned long long g_edge[EMAX];  // r:17 | c:17<<17 | rank<<34
__device__ __align__(16) float              g_dinv[NMAX];
__device__ __align__(16) float              g_xn[NMAX * 2];
__device__ __align__(16) __half             g_h2n[NMAX * 32];
__device__ __align__(16) __half             g_na[NMAX * 16];
__device__ __align__(16) __half             g_nb[NMAX * 16];

// ---------------------------------------------------------------------------
// decode edge_index; histogram in-degree; pack (r, c, rank) into u64.
// Also resets the scan status array (threads gid < NBLK).
// dtype probe is block-local: int64 data has all-zero odd 32-bit words;
// int32 data (random indices) fails that for 256 samples with P ~ 1e-1280.
__global__ void k_prep(const void* __restrict__ ei, int e) {
    int i = blockIdx.x * blockDim.x + threadIdx.x;
    if (i < NBLK) g_status[i] = 0ull;
    bool nz = false;
    if (i < e) {
        nz = (reinterpret_cast<const unsigned*>(ei)[2 * (size_t)i + 1] != 0u);
    }
    bool i64 = !__syncthreads_or((int)nz);
    if (i >= e) return;
    unsigned r, c;
    if (i64) {
        r = (unsigned)(reinterpret_cast<const long long*>(ei)[i]);
        c = (unsigned)(reinterpret_cast<const long long*>(ei)[(size_t)e + i]);
    } else {
        r = (unsigned)reinterpret_cast<const int*>(ei)[i];
        c = (unsigned)reinterpret_cast<const int*>(ei)[(size_t)e + i];
    }
    unsigned rank = (unsigned)atomicAdd(&g_degi[c], 1);
    g_edge[i] = (unsigned long long)r | ((unsigned long long)c << 17)
              | ((unsigned long long)rank << 34);
}

// single-pass decoupled-lookback scan: local scan + publish aggregate +
// warp-parallel lookback sum of predecessors; writes start, dinv, xn.
// Also re-zeroes degi (its last reader) for the next run/replay.
// Deadlock-free: 391 blocks of 256 threads are all co-resident.
__global__ void k_scan(const float* __restrict__ x, int n, int e) {
    __shared__ int ws[8];
    __shared__ int s_boff;
    int t = threadIdx.x;
    int lane = t & 31, wid = t >> 5;
    int b = blockIdx.x;
    if (b == 0 && t == 0) g_start[n] = e;

    int i = b * 256 + t;
    int v = (i < n) ? g_degi[i] : 0;
    if (i < n) g_degi[i] = 0;          // reset for next run (last reader)

    // local inclusive scan
    int s = v;
#pragma unroll
    for (int o = 1; o < 32; o <<= 1) {
        int u = __shfl_up_sync(0xFFFFFFFFu, s, o);
        if (lane >= o) s += u;
    }
    if (lane == 31) ws[wid] = s;
    __syncthreads();
    if (wid == 0 && lane < 8) {
        int w = ws[lane];
#pragma unroll
        for (int o = 1; o < 8; o <<= 1) {
            int u = __shfl_up_sync(0x000000FFu, w, o);
            if (lane >= o) w += u;
        }
        ws[lane] = w;
    }
    __syncthreads();

    // publish this block's aggregate (flag=1 | sum)
    if (t == 0) {
        unsigned long long pub = (1ull << 32) | (unsigned long long)(unsigned)ws[7];
        atomicExch(&g_status[b], pub);
    }

    // warp-parallel lookback: sum aggregates of blocks [0, b)
    if (wid == 0) {
        int sum = 0;
        for (int base = 0; base < b; base += 32) {
            int j = base + lane;
            int val = 0;
            if (j < b) {
                volatile unsigned long long* p = &g_status[j];
                unsigned long long sv = *p;
                while ((sv >> 32) == 0ull) { __nanosleep(32); sv = *p; }
                val = (int)(unsigned)sv;
            }
#pragma unroll
            for (int o = 16; o > 0; o >>= 1)
                val += __shfl_down_sync(0xFFFFFFFFu, val, o);
            if (lane == 0) sum += val;
        }
        if (lane == 0) s_boff = sum;
    }
    __syncthreads();

    int excl = s_boff + (wid ? ws[wid - 1] : 0) + s - v;
    if (i < n) {
        g_start[i] = excl;
        float di = rsqrtf((float)(v + 1));
        g_dinv[i] = di;
        float2 xv = reinterpret_cast<const float2*>(x)[i];
        reinterpret_cast<float2*>(g_xn)[i] = make_float2(di * xv.x, di * xv.y);
    }
}

// scatter edges into CSR slots — atomic-free
__global__ void k_scatter(int e) {
    int i = blockIdx.x * blockDim.x + threadIdx.x;
    if (i >= e) return;
    unsigned long long v = g_edge[i];
    int r = (int)(v & 0x1FFFFu);
    int c = (int)((v >> 17) & 0x1FFFFu);
    int rank = (int)(v >> 34);
    g_srcs[g_start[c] + rank] = r;
}

// layer 1 fused: gather xn (unroll-4), GEMV, write fp16 h2n
__global__ void k_layer1(const float* __restrict__ W1,  // [2,64]
                         const float* __restrict__ b1,  // [64]
                         const float* __restrict__ W2,  // [64,32]
                         int n) {
    __shared__ float sW1[128];
    __shared__ float sb1[64];
    __shared__ float sW2[2048];
    int t = threadIdx.x;
    for (int i = t; i < 128; i += blockDim.x) sW1[i] = W1[i];
    for (int i = t; i < 64; i += blockDim.x) sb1[i] = b1[i];
    for (int i = t; i < 2048; i += blockDim.x) sW2[i] = W2[i];
    __syncthreads();

    int nn = blockIdx.x * blockDim.x + t;
    if (nn >= n) return;
    int s0 = g_start[nn], s1 = g_start[nn + 1];
    float a0 = 0.0f, a1 = 0.0f;
    int j = s0;
    for (; j + 4 <= s1; j += 4) {
        int r0 = g_srcs[j], r1 = g_srcs[j + 1], r2 = g_srcs[j + 2], r3 = g_srcs[j + 3];
        float2 v0 = reinterpret_cast<const float2*>(g_xn)[r0];
        float2 v1 = reinterpret_cast<const float2*>(g_xn)[r1];
        float2 v2 = reinterpret_cast<const float2*>(g_xn)[r2];
        float2 v3 = reinterpret_cast<const float2*>(g_xn)[r3];
        a0 += (v0.x + v1.x) + (v2.x + v3.x);
        a1 += (v0.y + v1.y) + (v2.y + v3.y);
    }
    for (; j < s1; j++) {
        float2 v = reinterpret_cast<const float2*>(g_xn)[g_srcs[j]];
        a0 += v.x; a1 += v.y;
    }
    float di = g_dinv[nn];
    float2 xv = reinterpret_cast<const float2*>(g_xn)[nn];
    float v0 = di * (a0 + xv.x);
    float v1 = di * (a1 + xv.y);

    float acc[32];
#pragma unroll
    for (int k = 0; k < 32; k++) acc[k] = 0.0f;
#pragma unroll 4
    for (int jj = 0; jj < 64; jj++) {
        float h = fmaxf(fmaf(v0, sW1[jj], fmaf(v1, sW1[64 + jj], sb1[jj])), 0.0f);
#pragma unroll
        for (int k = 0; k < 32; k++) acc[k] = fmaf(h, sW2[jj * 32 + k], acc[k]);
    }

    __half2 hp[16];
#pragma unroll
    for (int k = 0; k < 16; k++)
        hp[k] = __floats2half2_rn(di * acc[2 * k], di * acc[2 * k + 1]);
    uint4* o = reinterpret_cast<uint4*>(g_h2n + (size_t)nn * 32);
    const uint4* src = reinterpret_cast<const uint4*>(hp);
#pragma unroll
    for (int k = 0; k < 4; k++) o[k] = src[k];
}

__device__ __forceinline__ void acc_slice(float* acc, uint4 raw) {
    const __half2* hh = reinterpret_cast<const __half2*>(&raw);
#pragma unroll
    for (int k = 0; k < 4; k++) {
        float2 f = __half22float2(hh[k]);
        acc[2 * k] += f.x; acc[2 * k + 1] += f.y;
    }
}

// layer 2 fused, 4 threads/node, gather unroll-4 (MLP 4)
__global__ void k_layer2(const float* __restrict__ mW1,  // [65,16]
                         const float* __restrict__ b2,   // [32]
                         int n) {
    __shared__ float sAB[1024];
    __shared__ float sb2[32];
    __shared__ float sh[64 * 32];
    int t = threadIdx.x;
    for (int idx = t; idx < 1024; idx += blockDim.x) {
        int k = idx >> 5, i = idx & 31;
        sAB[idx] = (i < 16) ? mW1[k * 16 + i] : mW1[(32 + k) * 16 + (i - 16)];
    }
    for (int i = t; i < 32; i += blockDim.x) sb2[i] = b2[i];
    __syncthreads();

    int local = t >> 2;
    int p = t & 3;
    int nn = blockIdx.x * 64 + local;
    bool active = (nn < n);

    if (active) {
        int s0 = g_start[nn], s1 = g_start[nn + 1];
        float acc[8];
        {
            uint4 raw = reinterpret_cast<const uint4*>(g_h2n + (size_t)nn * 32)[p];
            const __half2* hh = reinterpret_cast<const __half2*>(&raw);
#pragma unroll
            for (int k = 0; k < 4; k++) {
                float2 f = __half22float2(hh[k]);
                acc[2 * k] = f.x; acc[2 * k + 1] = f.y;
            }
        }
        int j = s0;
        for (; j + 4 <= s1; j += 4) {
            int r0 = g_srcs[j], r1 = g_srcs[j + 1], r2 = g_srcs[j + 2], r3 = g_srcs[j + 3];
            uint4 w0 = reinterpret_cast<const uint4*>(g_h2n + (size_t)r0 * 32)[p];
            uint4 w1 = reinterpret_cast<const uint4*>(g_h2n + (size_t)r1 * 32)[p];
            uint4 w2 = reinterpret_cast<const uint4*>(g_h2n + (size_t)r2 * 32)[p];
            uint4 w3 = reinterpret_cast<const uint4*>(g_h2n + (size_t)r3 * 32)[p];
            acc_slice(acc, w0);
            acc_slice(acc, w1);
            acc_slice(acc, w2);
            acc_slice(acc, w3);
        }
        for (; j < s1; j++) {
            int r0 = g_srcs[j];
            acc_slice(acc, reinterpret_cast<const uint4*>(g_h2n + (size_t)r0 * 32)[p]);
        }
        float di = g_dinv[nn];
#pragma unroll
        for (int k = 0; k < 8; k++)
            sh[local * 32 + 8 * p + k] = fmaxf(fmaf(di, acc[k], sb2[8 * p + k]), 0.0f);
    }
    __syncthreads();

    if (active) {
        float o8[8];
#pragma unroll
        for (int i = 0; i < 8; i++) o8[i] = 0.0f;
        const float* hrow = sh + local * 32;
#pragma unroll 8
        for (int k = 0; k < 32; k++) {
            float h = hrow[k];
            const float* w = sAB + k * 32 + 8 * p;
#pragma unroll
            for (int i = 0; i < 8; i++) o8[i] = fmaf(h, w[i], o8[i]);
        }
        __half2 hp[4];
#pragma unroll
        for (int k = 0; k < 4; k++)
            hp[k] = __floats2half2_rn(o8[2 * k], o8[2 * k + 1]);
        __half* base = (p < 2) ? (g_na + (size_t)nn * 16 + 8 * p)
                               : (g_nb + (size_t)nn * 16 + 8 * (p - 2));
        *reinterpret_cast<uint4*>(base) = *reinterpret_cast<const uint4*>(hp);
    }
}

// per edge, 2 threads/edge: lane p loads 16B slice p of na[r] and nb[c]
// (pair hits the same 128B line -> half the L1tex wavefronts), computes
// 8 hidden units, shfl-combines, lane 0 writes sigmoid.
__global__ void k_edge(const float* __restrict__ ea,
                       const float* __restrict__ mW1,
                       const float* __restrict__ mb1,
                       const float* __restrict__ mW2,
                       const float* __restrict__ mb2,
                       float* __restrict__ out, int e) {
    __shared__ float sw64[16], smb1[16], smw2[16];
    __shared__ float smb2;
    int t = threadIdx.x;
    if (t < 16) {
        sw64[t] = mW1[64 * 16 + t];
        smb1[t] = mb1[t];
        smw2[t] = mW2[t];
    }
    if (t == 0) smb2 = mb2[0];
    __syncthreads();

    int i = blockIdx.x * 128 + (t >> 1);   // edge index
    int p = t & 1;                          // slice
    if (i >= e) return;
    unsigned long long v = g_edge[i];
    int r = (int)(v & 0x1FFFFu);
    int c = (int)((v >> 17) & 0x1FFFFu);
    float attr = ea[i];

    uint4 ra = reinterpret_cast<const uint4*>(g_na + (size_t)r * 16)[p];
    uint4 rb = reinterpret_cast<const uint4*>(g_nb + (size_t)c * 16)[p];
    const __half2* ha = reinterpret_cast<const __half2*>(&ra);
    const __half2* hb = reinterpret_cast<const __half2*>(&rb);

    int k0 = 8 * p;
    float s = 0.0f;
#pragma unroll
    for (int q = 0; q < 4; q++) {
        float2 av = __half22float2(ha[q]);
        float2 bv = __half22float2(hb[q]);
        float h;
        h = fmaxf(av.x + bv.x + fmaf(attr, sw64[k0 + 2 * q], smb1[k0 + 2 * q]), 0.0f);
        s = fmaf(h, smw2[k0 + 2 * q], s);
        h = fmaxf(av.y + bv.y + fmaf(attr, sw64[k0 + 2 * q + 1], smb1[k0 + 2 * q + 1]), 0.0f);
        s = fmaf(h, smw2[k0 + 2 * q + 1], s);
    }
    s += __shfl_xor_sync(0xFFFFFFFFu, s, 1);
    if (p == 0) {
        float z = s + smb2;
        out[i] = 1.0f / (1.0f + __expf(-z));
    }
}

// ---------------------------------------------------------------------------
extern "C" void kernel_launch(void* const* d_in, const int* in_sizes, int n_in,
                              void* d_out, int out_size) {
    const float* x = (const float*)d_in[0];
    const void* ei = d_in[1];
    const float* ea = (const float*)d_in[2];

    int base = (in_sizes[3] == 128) ? 3 : 4;
    const float* W1 = (const float*)d_in[base + 0];
    const float* b1 = (const float*)d_in[base + 1];
    const float* W2 = (const float*)d_in[base + 2];
    const float* b2 = (const float*)d_in[base + 3];
    const float* mW1 = (const float*)d_in[base + 4];
    const float* mb1 = (const float*)d_in[base + 5];
    const float* mW2 = (const float*)d_in[base + 6];
    const float* mb2 = (const float*)d_in[base + 7];

    int n = in_sizes[0] / 2;
    int e = in_sizes[1] / 2;
    float* out = (float*)d_out;

    const int B = 256;
    int gn = (n + B - 1) / B;
    int ge = (e + B - 1) / B;
    int gn4 = (n + 63) / 64;
    int ge2 = (e + 127) / 128;         // 2 threads per edge

    k_prep<<<ge, B>>>(ei, e);
    k_scan<<<gn, B>>>(x, n, e);
    k_scatter<<<ge, B>>>(e);
    k_layer1<<<gn, B>>>(W1, b1, W2, n);
    k_layer2<<<gn4, B>>>(mW1, b2, n);
    k_edge<<<ge2, B>>>(ea, mW1, mb1, mW2, mb2, out, e);
}